// round 2
// baseline (speedup 1.0000x reference)
#include <cuda_runtime.h>

#define BATCH   4
#define NPTS    8192
#define NPAIRS  (NPTS / 2)
#define THREADS 256
#define IX      2
#define TILES   (NPTS / (THREADS * IX))   // 16 query tiles per (batch, direction)

typedef unsigned long long u64;

// ---- packed f32x2 helpers (sm_100+ only via PTX) ----
__device__ __forceinline__ u64 pack2(float lo, float hi) {
    u64 r;
    asm("mov.b64 %0, {%1, %2};" : "=l"(r) : "f"(lo), "f"(hi));
    return r;
}
__device__ __forceinline__ u64 ffma2(u64 a, u64 b, u64 c) {
    u64 d;
    asm("fma.rn.f32x2 %0, %1, %2, %3;" : "=l"(d) : "l"(a), "l"(b), "l"(c));
    return d;
}
__device__ __forceinline__ float2 unpack2(u64 v) {
    float2 f;
    asm("mov.b64 {%0, %1}, %2;" : "=f"(f.x), "=f"(f.y) : "l"(v));
    return f;
}

// d_out is poisoned to 0xAA; zero it before accumulation.
__global__ void zero_out_kernel(float* out) { *out = 0.0f; }

// One block = (batch, direction, query tile). Stages ALL 8192 targets into
// smem in point-pair SoA form:
//   sA[p] = (x_{2p}, x_{2p+1}, y_{2p}, y_{2p+1})
//   sB[p] = (z_{2p}, z_{2p+1}, w_{2p}, w_{2p+1})   with w = ||t||^2
// Inner loop evaluates 2 points x 2 queries per iteration with packed
// fma.rn.f32x2 (FFMA2): v = w - 2 q.t ; min-reduce with split accumulators.
__global__ __launch_bounds__(THREADS) void chamfer_kernel(
    const float* __restrict__ x, const float* __restrict__ y,
    float* __restrict__ out)
{
    extern __shared__ float4 smem[];          // 2 * NPAIRS float4 = 128 KB
    float4* sA = smem;
    float4* sB = smem + NPAIRS;

    const int bid  = blockIdx.x;
    const int tile = bid % TILES;
    const int dir  = (bid / TILES) & 1;
    const int b    = bid / (TILES * 2);

    const float* q = (dir ? y : x) + (size_t)b * NPTS * 3;
    const float* t = (dir ? x : y) + (size_t)b * NPTS * 3;

    // Stage targets in pair-SoA layout with precomputed squared norm.
    {
        float* sAf = (float*)sA;
        float* sBf = (float*)sB;
        for (int j = threadIdx.x; j < NPTS; j += THREADS) {
            float tx = t[3 * j + 0];
            float ty = t[3 * j + 1];
            float tz = t[3 * j + 2];
            float w  = fmaf(tx, tx, fmaf(ty, ty, tz * tz));
            int p = j >> 1, h = j & 1;
            sAf[4 * p + 0 + h] = tx;
            sAf[4 * p + 2 + h] = ty;
            sBf[4 * p + 0 + h] = tz;
            sBf[4 * p + 2 + h] = w;
        }
    }
    __syncthreads();

    // Two queries per thread.
    const int q0 = tile * (THREADS * IX) + threadIdx.x;
    const int q1 = q0 + THREADS;

    const float qx0 = q[3 * q0 + 0], qy0 = q[3 * q0 + 1], qz0 = q[3 * q0 + 2];
    const float qx1 = q[3 * q1 + 0], qy1 = q[3 * q1 + 1], qz1 = q[3 * q1 + 2];

    const float w0 = fmaf(qx0, qx0, fmaf(qy0, qy0, qz0 * qz0));
    const float w1 = fmaf(qx1, qx1, fmaf(qy1, qy1, qz1 * qz1));

    // Loop-invariant packed coefficients (-2*q broadcast into both lanes).
    const u64 ax0p = pack2(-2.0f * qx0, -2.0f * qx0);
    const u64 ay0p = pack2(-2.0f * qy0, -2.0f * qy0);
    const u64 az0p = pack2(-2.0f * qz0, -2.0f * qz0);
    const u64 ax1p = pack2(-2.0f * qx1, -2.0f * qx1);
    const u64 ay1p = pack2(-2.0f * qy1, -2.0f * qy1);
    const u64 az1p = pack2(-2.0f * qz1, -2.0f * qz1);

    const float FMAX = 3.402823466e+38f;
    float m0a = FMAX, m0b = FMAX, m1a = FMAX, m1b = FMAX;

    const ulonglong2* sA64 = (const ulonglong2*)sA;
    const ulonglong2* sB64 = (const ulonglong2*)sB;

#pragma unroll 8
    for (int p = 0; p < NPAIRS; ++p) {
        const ulonglong2 A = sA64[p];   // LDS.128: (Tx pair, Ty pair)
        const ulonglong2 B = sB64[p];   // LDS.128: (Tz pair, Tw pair)

        u64 v0 = ffma2(az0p, A.y /*dummy*/, B.y);  // placeholder replaced below
        // correct chains:
        v0       = ffma2(az0p, B.x, B.y);
        v0       = ffma2(ay0p, A.y, v0);
        v0       = ffma2(ax0p, A.x, v0);
        u64 v1   = ffma2(az1p, B.x, B.y);
        v1       = ffma2(ay1p, A.y, v1);
        v1       = ffma2(ax1p, A.x, v1);

        const float2 f0 = unpack2(v0);
        const float2 f1 = unpack2(v1);
        m0a = fminf(m0a, f0.x);
        m0b = fminf(m0b, f0.y);
        m1a = fminf(m1a, f1.x);
        m1b = fminf(m1b, f1.y);
    }

    const float m0 = fminf(m0a, m0b);
    const float m1 = fminf(m1a, m1b);
    float s = fmaxf(m0 + w0, 0.0f) + fmaxf(m1 + w1, 0.0f);

    // Warp reduction then cross-warp reduction.
#pragma unroll
    for (int o = 16; o > 0; o >>= 1)
        s += __shfl_xor_sync(0xffffffffu, s, o);

    __shared__ float red[THREADS / 32];
    if ((threadIdx.x & 31) == 0) red[threadIdx.x >> 5] = s;
    __syncthreads();

    if (threadIdx.x < THREADS / 32) {
        s = red[threadIdx.x];
#pragma unroll
        for (int o = (THREADS / 32) / 2; o > 0; o >>= 1)
            s += __shfl_xor_sync(0xffu, s, o);
        if (threadIdx.x == 0)
            atomicAdd(out, s * (1.0f / (float)(BATCH * NPTS)));
    }
}

extern "C" void kernel_launch(void* const* d_in, const int* in_sizes, int n_in,
                              void* d_out, int out_size)
{
    (void)in_sizes; (void)n_in; (void)out_size;
    const float* x = (const float*)d_in[0];
    const float* y = (const float*)d_in[1];
    float* out = (float*)d_out;

    zero_out_kernel<<<1, 1>>>(out);

    const int smem = 2 * NPAIRS * (int)sizeof(float4);  // 131072 bytes
    cudaFuncSetAttribute(chamfer_kernel,
                         cudaFuncAttributeMaxDynamicSharedMemorySize, smem);

    chamfer_kernel<<<BATCH * 2 * TILES, THREADS, smem>>>(x, y, out);
}

// round 3
// speedup vs baseline: 1.7231x; 1.7231x over previous
#include <cuda_runtime.h>
#include <float.h>

#define NPTS    8192
#define NCHUNK  37        // target chunks per (batch,dir): 8*4*37 = 1184 = 148*8
#define QTILES  4
#define QTILE   2048      // queries per block = THREADS * IX
#define THREADS 256
#define IX      8
#define COMBOS  8         // 4 batches * 2 directions
#define GRID1   (COMBOS * QTILES * NCHUNK)

// Partial mins: [chunk][global query]. Each cell written by exactly one block.
__device__ float g_partial[NCHUNK][COMBOS * NPTS];   // ~9.7 MB

__global__ void zero_out_kernel(float* out) { *out = 0.0f; }

// Block = (combo, qtile, chunk). Stages ~222 targets (float4: x,y,z,||t||^2),
// computes min over the chunk of (||t||^2 - 2 q.t) for 2048 queries (8/thread),
// writes partial mins to scratch. Pure fma-pipe bound: 24 FFMA per staged point
// per warp vs 1 LDS.128.
__global__ __launch_bounds__(THREADS) void chamfer_partial(
    const float* __restrict__ x, const float* __restrict__ y)
{
    __shared__ float4 sT[224];

    const int bid   = blockIdx.x;
    const int chunk = bid % NCHUNK;
    const int qtile = (bid / NCHUNK) % QTILES;
    const int combo = bid / (NCHUNK * QTILES);
    const int dir   = combo & 1;
    const int b     = combo >> 1;

    const float* q = (dir ? y : x) + (size_t)b * NPTS * 3;
    const float* t = (dir ? x : y) + (size_t)b * NPTS * 3;

    const int j0  = (NPTS * chunk) / NCHUNK;
    const int j1  = (NPTS * (chunk + 1)) / NCHUNK;
    const int cnt = j1 - j0;          // 221 or 222

    if (threadIdx.x < cnt) {
        const int j = j0 + threadIdx.x;
        const float tx = t[3 * j + 0];
        const float ty = t[3 * j + 1];
        const float tz = t[3 * j + 2];
        sT[threadIdx.x] = make_float4(tx, ty, tz,
                                      fmaf(tx, tx, fmaf(ty, ty, tz * tz)));
    }
    __syncthreads();

    float ax[IX], ay[IX], az[IX], mn[IX];
    const int qbase = qtile * QTILE + threadIdx.x;
#pragma unroll
    for (int i = 0; i < IX; ++i) {
        const int qi = qbase + i * THREADS;
        ax[i] = -2.0f * q[3 * qi + 0];
        ay[i] = -2.0f * q[3 * qi + 1];
        az[i] = -2.0f * q[3 * qi + 2];
        mn[i] = FLT_MAX;
    }

#pragma unroll 4
    for (int p = 0; p < cnt; ++p) {
        const float4 T = sT[p];       // warp-broadcast LDS.128
#pragma unroll
        for (int i = 0; i < IX; ++i) {
            const float v = fmaf(ax[i], T.x,
                            fmaf(ay[i], T.y,
                            fmaf(az[i], T.z, T.w)));
            mn[i] = fminf(mn[i], v);
        }
    }

    const int gq = combo * NPTS + qbase;
#pragma unroll
    for (int i = 0; i < IX; ++i)
        g_partial[chunk][gq + i * THREADS] = mn[i];
}

// Combine 37 partials per query, add ||q||^2, clamp, sum, scale, accumulate.
__global__ __launch_bounds__(256) void chamfer_reduce(
    const float* __restrict__ x, const float* __restrict__ y,
    float* __restrict__ out)
{
    const int gq = blockIdx.x * 256 + threadIdx.x;

    float m = FLT_MAX;
#pragma unroll
    for (int c = 0; c < NCHUNK; ++c)
        m = fminf(m, g_partial[c][gq]);

    const int combo = gq >> 13;
    const int dir   = combo & 1;
    const int b     = combo >> 1;
    const int qi    = gq & (NPTS - 1);
    const float* q  = (dir ? y : x) + (size_t)b * NPTS * 3;

    const float qx = q[3 * qi + 0];
    const float qy = q[3 * qi + 1];
    const float qz = q[3 * qi + 2];
    const float w  = fmaf(qx, qx, fmaf(qy, qy, qz * qz));

    float v = fmaxf(m + w, 0.0f);

#pragma unroll
    for (int o = 16; o > 0; o >>= 1)
        v += __shfl_xor_sync(0xffffffffu, v, o);

    __shared__ float red[8];
    if ((threadIdx.x & 31) == 0) red[threadIdx.x >> 5] = v;
    __syncthreads();

    if (threadIdx.x < 8) {
        v = red[threadIdx.x];
#pragma unroll
        for (int o = 4; o > 0; o >>= 1)
            v += __shfl_xor_sync(0xffu, v, o);
        if (threadIdx.x == 0)
            atomicAdd(out, v * (1.0f / (float)(COMBOS * NPTS / 2)));
    }
}

extern "C" void kernel_launch(void* const* d_in, const int* in_sizes, int n_in,
                              void* d_out, int out_size)
{
    (void)in_sizes; (void)n_in; (void)out_size;
    const float* x = (const float*)d_in[0];
    const float* y = (const float*)d_in[1];
    float* out = (float*)d_out;

    zero_out_kernel<<<1, 1>>>(out);
    chamfer_partial<<<GRID1, THREADS>>>(x, y);
    chamfer_reduce<<<(COMBOS * NPTS) / 256, 256>>>(x, y, out);
}

// round 4
// speedup vs baseline: 1.8536x; 1.0758x over previous
#include <cuda_runtime.h>
#include <float.h>

#define NPTS    8192
#define NB      4
#define NCHUNK  37                 // 4*4*37 = 592 = 148*4 blocks
#define NTILES  4
#define THREADS 256
#define IX      8
#define GRID1   (NB * NTILES * NCHUNK)
#define GRID2   256                // reduce: 65536 items / 256

// Scratch (written each run by exactly one block per cell; no init needed).
__device__ float g_rowpart[NCHUNK][NB * NPTS];   // min_m(u) per chunk, u = wm - 2 x.y
__device__ float g_colpart[NTILES][NB * NPTS];   // min_n(d2) per n-tile (full d2)
__device__ float    g_sum = 0.0f;                // reset by last reduce block
__device__ unsigned g_cnt = 0;

// One pass over each batch's 8192x8192 distance matrix. Block = (b, ntile, chunk).
// Stages ~222 y-points (x,y,z,||y||^2). Each thread owns 8 x-queries.
// Per pair: u = wm - 2 x.y (3 FFMA), row-min on u (alu), d2 = u + wn (1 FADD),
// col-min via 8-way tree + warp shfl-min + per-warp smem slot.
__global__ __launch_bounds__(THREADS, 4) void chamfer_main(
    const float* __restrict__ x, const float* __restrict__ y)
{
    __shared__ float4 sT[224];
    __shared__ float  sCol[8][224];

    const int bid   = blockIdx.x;
    const int chunk = bid % NCHUNK;
    const int ntile = (bid / NCHUNK) % NTILES;
    const int b     = bid / (NCHUNK * NTILES);

    const float* q = x + (size_t)b * NPTS * 3;
    const float* t = y + (size_t)b * NPTS * 3;

    const int j0  = (NPTS * chunk) / NCHUNK;
    const int j1  = (NPTS * (chunk + 1)) / NCHUNK;
    const int cnt = j1 - j0;                      // 221 or 222

    if (threadIdx.x < cnt) {
        const int j = j0 + threadIdx.x;
        const float tx = t[3 * j + 0];
        const float ty = t[3 * j + 1];
        const float tz = t[3 * j + 2];
        sT[threadIdx.x] = make_float4(tx, ty, tz,
                                      fmaf(tx, tx, fmaf(ty, ty, tz * tz)));
    }
    __syncthreads();

    float ax[IX], ay[IX], az[IX], wn[IX], rm[IX];
    const int qbase = ntile * (THREADS * IX) + threadIdx.x;
#pragma unroll
    for (int i = 0; i < IX; ++i) {
        const int qi = qbase + i * THREADS;
        const float qx = q[3 * qi + 0];
        const float qy = q[3 * qi + 1];
        const float qz = q[3 * qi + 2];
        ax[i] = -2.0f * qx;
        ay[i] = -2.0f * qy;
        az[i] = -2.0f * qz;
        wn[i] = fmaf(qx, qx, fmaf(qy, qy, qz * qz));
        rm[i] = FLT_MAX;
    }

    const int wid  = threadIdx.x >> 5;
    const int lane = threadIdx.x & 31;

#pragma unroll 2
    for (int p = 0; p < cnt; ++p) {
        const float4 T = sT[p];                 // warp-broadcast LDS.128
        float tt[IX];
#pragma unroll
        for (int i = 0; i < IX; ++i) {
            const float u = fmaf(ax[i], T.x,
                            fmaf(ay[i], T.y,
                            fmaf(az[i], T.z, T.w)));
            rm[i]  = fminf(rm[i], u);           // row candidate (wn added later)
            tt[i]  = u + wn[i];                 // full d2: col candidate
        }
        // 8 -> 1 tree min (alu pipe)
        float a0 = fminf(tt[0], tt[1]);
        float a1 = fminf(tt[2], tt[3]);
        float a2 = fminf(tt[4], tt[5]);
        float a3 = fminf(tt[6], tt[7]);
        float tmin = fminf(fminf(a0, a1), fminf(a2, a3));
        // warp min
#pragma unroll
        for (int o = 16; o > 0; o >>= 1)
            tmin = fminf(tmin, __shfl_xor_sync(0xffffffffu, tmin, o));
        if (lane == 0) sCol[wid][p] = tmin;
    }
    __syncthreads();

    const int gq = b * NPTS + qbase;
#pragma unroll
    for (int i = 0; i < IX; ++i)
        g_rowpart[chunk][gq + i * THREADS] = rm[i];

    if (threadIdx.x < cnt) {
        float m = sCol[0][threadIdx.x];
#pragma unroll
        for (int w = 1; w < 8; ++w)
            m = fminf(m, sCol[w][threadIdx.x]);
        g_colpart[ntile][b * NPTS + j0 + threadIdx.x] = m;
    }
}

// 65536 items: [0,32768) row queries (min over 37 chunks, +wn, clamp),
// [32768,65536) col queries (min over 4 tiles, clamp). Last block writes out.
__global__ __launch_bounds__(256) void chamfer_reduce(
    const float* __restrict__ x, float* __restrict__ out)
{
    const int idx = blockIdx.x * 256 + threadIdx.x;

    float v;
    if (idx < NB * NPTS) {
        float m = FLT_MAX;
#pragma unroll
        for (int c = 0; c < NCHUNK; ++c)
            m = fminf(m, g_rowpart[c][idx]);
        const int b = idx >> 13, n = idx & (NPTS - 1);
        const float* q = x + (size_t)b * NPTS * 3;
        const float qx = q[3 * n + 0];
        const float qy = q[3 * n + 1];
        const float qz = q[3 * n + 2];
        v = fmaxf(m + fmaf(qx, qx, fmaf(qy, qy, qz * qz)), 0.0f);
    } else {
        const int j = idx - NB * NPTS;
        float m = g_colpart[0][j];
#pragma unroll
        for (int c = 1; c < NTILES; ++c)
            m = fminf(m, g_colpart[c][j]);
        v = fmaxf(m, 0.0f);
    }

#pragma unroll
    for (int o = 16; o > 0; o >>= 1)
        v += __shfl_xor_sync(0xffffffffu, v, o);

    __shared__ float red[8];
    if ((threadIdx.x & 31) == 0) red[threadIdx.x >> 5] = v;
    __syncthreads();

    if (threadIdx.x < 8) {
        v = red[threadIdx.x];
#pragma unroll
        for (int o = 4; o > 0; o >>= 1)
            v += __shfl_xor_sync(0xffu, v, o);
        if (threadIdx.x == 0) {
            atomicAdd(&g_sum, v);
            __threadfence();
            const unsigned old = atomicAdd(&g_cnt, 1u);
            if (old == GRID2 - 1) {
                // all partial sums visible (their g_sum adds precede their g_cnt adds)
                const float total = *(volatile float*)&g_sum;
                *out = total * (1.0f / (float)(NB * NPTS * 2 / 2) / 2.0f * 2.0f / 2.0f); // placeholder
                // correct scale: sum of 65536 clamped mins / (NPTS * NB)  [row mean + col mean per batch, /NB]
                *out = total * (1.0f / ((float)NPTS * (float)NB));
                g_sum = 0.0f;        // reset for next graph replay
                g_cnt = 0u;
            }
        }
    }
}

extern "C" void kernel_launch(void* const* d_in, const int* in_sizes, int n_in,
                              void* d_out, int out_size)
{
    (void)in_sizes; (void)n_in; (void)out_size;
    const float* x = (const float*)d_in[0];
    const float* y = (const float*)d_in[1];
    float* out = (float*)d_out;

    chamfer_main<<<GRID1, THREADS>>>(x, y);
    chamfer_reduce<<<GRID2, 256>>>(x, out);
}